// round 15
// baseline (speedup 1.0000x reference)
#include <cuda_runtime.h>
#include <cuda_fp16.h>
#include <cstdint>
#include <math.h>

#define BB 2
#define SS 2048
#define EE 1024
#define HH 16
#define DD 64
#define NQKV 3072

// ---------------------------------------------------------------------------
// Scratch (device globals — allocation-free). Plain fp16 everywhere.
// ---------------------------------------------------------------------------
__device__ __half g_x16[BB*SS*EE];       // x
__device__ __half g_wq16[EE*NQKV];       // w_qkv
__device__ __half g_wo16[EE*EE];         // w_out
__device__ __half g_q16[BB*HH*SS*DD];    // Q (pre-scaled by 0.125*log2e)
__device__ __half g_k16[BB*HH*SS*DD];
__device__ __half g_v16[BB*HH*SS*DD];
__device__ __half g_o16[BB*SS*EE];       // attention output

// single TU-wide dynamic smem symbol (char) — cast per kernel
extern __shared__ __align__(16) char dynsmem[];

// ---------------------------------------------------------------------------
// PTX wrappers
// ---------------------------------------------------------------------------
__device__ __forceinline__ void ldsm4(unsigned r[4], uint32_t a) {
    asm volatile("ldmatrix.sync.aligned.m8n8.x4.shared.b16 {%0,%1,%2,%3}, [%4];\n"
                 : "=r"(r[0]), "=r"(r[1]), "=r"(r[2]), "=r"(r[3]) : "r"(a));
}
__device__ __forceinline__ void ldsm4t(unsigned r[4], uint32_t a) {
    asm volatile("ldmatrix.sync.aligned.m8n8.x4.trans.shared.b16 {%0,%1,%2,%3}, [%4];\n"
                 : "=r"(r[0]), "=r"(r[1]), "=r"(r[2]), "=r"(r[3]) : "r"(a));
}
__device__ __forceinline__ void mma_f16(float c[4], const unsigned a[4], const unsigned b[2]) {
    asm volatile(
        "mma.sync.aligned.m16n8k16.row.col.f32.f16.f16.f32 "
        "{%0,%1,%2,%3}, {%4,%5,%6,%7}, {%8,%9}, {%0,%1,%2,%3};\n"
        : "+f"(c[0]), "+f"(c[1]), "+f"(c[2]), "+f"(c[3])
        : "r"(a[0]), "r"(a[1]), "r"(a[2]), "r"(a[3]), "r"(b[0]), "r"(b[1]));
}
__device__ __forceinline__ void cp16(uint32_t s, const void* g) {
    asm volatile("cp.async.cg.shared.global [%0], [%1], 16;\n" :: "r"(s), "l"(g));
}
__device__ __forceinline__ void cp_commit() {
    asm volatile("cp.async.commit_group;\n" ::: "memory");
}
template <int N>
__device__ __forceinline__ void cp_wait() {
    asm volatile("cp.async.wait_group %0;\n" :: "n"(N) : "memory");
}
__device__ __forceinline__ unsigned pack_h2(float x, float y) {
    __half2 h2 = __floats2half2_rn(x, y);
    return *reinterpret_cast<unsigned*>(&h2);
}
__device__ __forceinline__ unsigned h2_ex2(unsigned in) {
    unsigned out;
    asm("ex2.approx.f16x2 %0, %1;" : "=r"(out) : "r"(in));
    return out;
}
__device__ __forceinline__ uint32_t smem_u32(const void* p) {
    return (uint32_t)__cvta_generic_to_shared(p);
}

// ---------------------------------------------------------------------------
// Merged fp32 -> fp16 convert for x, w_qkv, w_out (single launch)
// ---------------------------------------------------------------------------
#define CN1 (BB*SS*EE/4)
#define CN2 (EE*NQKV/4)
#define CN3 (EE*EE/4)

__global__ __launch_bounds__(256) void conv3_kernel(const float* __restrict__ s1,
                                                    const float* __restrict__ s2,
                                                    const float* __restrict__ s3,
                                                    __half* __restrict__ d1,
                                                    __half* __restrict__ d2,
                                                    __half* __restrict__ d3) {
    int i = blockIdx.x * 256 + threadIdx.x;
    const float* src;
    __half* dst;
    int j;
    if (i < CN1)              { src = s1; dst = d1; j = i; }
    else if (i < CN1 + CN2)   { src = s2; dst = d2; j = i - CN1; }
    else if (i < CN1+CN2+CN3) { src = s3; dst = d3; j = i - CN1 - CN2; }
    else return;
    float4 v = *(const float4*)(src + (size_t)j * 4);
    *(uint2*)(dst + (size_t)j * 4) =
        make_uint2(pack_h2(v.x, v.y), pack_h2(v.z, v.w));
}

// ---------------------------------------------------------------------------
// fp16 GEMM: C[M, NC] = A[M,1024] @ W[1024,NC]   (round-13 config)
// BM=128, BN=128, BK=64, 8 warps, warp tile 32x64, 2 CTAs/SM.
// 3-stage cp.async ring, depth-2 prefetch, 1 sync per 64-deep k-tile.
// ---------------------------------------------------------------------------
#define ST_A 9216                          // 128*72 elems
#define ST_B 8704                          // 64*136 elems
#define ST_BYTES ((ST_A + ST_B) * 2)       // 35840 B
#define G5_SMEM (3 * ST_BYTES)             // 107520 B

template <int NC, bool SCATTER>
__global__ __launch_bounds__(256, 2) void mma_gemm5(const __half* __restrict__ A_g,
                                                    const __half* __restrict__ B_g,
                                                    float* __restrict__ C) {
    char* smem = dynsmem;
    const int tid = threadIdx.x;
    const int lane = tid & 31, wid = tid >> 5;
    const int wm = (wid & 3) * 32, wn = (wid >> 2) * 64;
    const int m0 = blockIdx.y * 128, n0 = blockIdx.x * 128;

    const uint32_t uS = smem_u32(smem);
    const int lm_r = lane & 15, lm_c = (lane >> 4) * 8;
    const uint32_t aoff0 = ((wm + lm_r) * 72 + lm_c) * 2;
    const uint32_t boff0 = (lm_r * 136 + wn + lm_c) * 2;

    float acc[2][8][4];
#pragma unroll
    for (int i = 0; i < 2; i++)
#pragma unroll
        for (int j = 0; j < 8; j++)
#pragma unroll
            for (int q = 0; q < 4; q++) acc[i][j][q] = 0.0f;

    auto load_tile = [&](int slot, int k0) {
        uint32_t base = uS + slot * ST_BYTES;
#pragma unroll
        for (int i = 0; i < 4; i++) {
            int idx = tid + i * 256;
            int r = idx >> 3, c8 = (idx & 7) * 8;
            cp16(base + (r * 72 + c8) * 2,
                 A_g + (size_t)(m0 + r) * EE + k0 + c8);
        }
        uint32_t bbase = base + ST_A * 2;
#pragma unroll
        for (int i = 0; i < 4; i++) {
            int idx = tid + i * 256;
            int r = idx >> 4, c8 = (idx & 15) * 8;
            cp16(bbase + (r * 136 + c8) * 2,
                 B_g + (size_t)(k0 + r) * NC + n0 + c8);
        }
    };

    load_tile(0, 0);  cp_commit();
    load_tile(1, 64); cp_commit();

    int slot = 0, pslot = 2;
#pragma unroll 1
    for (int kt = 0; kt < 16; kt++) {
        if (kt < 15) cp_wait<1>(); else cp_wait<0>();
        __syncthreads();

        if (kt + 2 < 16) {
            load_tile(pslot, (kt + 2) * 64);
            cp_commit();
        }

        const uint32_t uA = uS + slot * ST_BYTES;
        const uint32_t uB = uA + ST_A * 2;

#pragma unroll
        for (int ks = 0; ks < 4; ks++) {
            const int kk = ks * 16;
            unsigned ah[2][4];
#pragma unroll
            for (int tm = 0; tm < 2; tm++) {
                uint32_t off = aoff0 + (tm * 16 * 72 + kk) * 2;
                ldsm4(ah[tm], uA + off);
            }
#pragma unroll
            for (int g = 0; g < 4; g++) {
                unsigned bh[4];
                uint32_t off = boff0 + (kk * 136 + g * 16) * 2;
                ldsm4t(bh, uB + off);
                mma_f16(acc[0][2 * g],     ah[0], &bh[0]);
                mma_f16(acc[0][2 * g + 1], ah[0], &bh[2]);
                mma_f16(acc[1][2 * g],     ah[1], &bh[0]);
                mma_f16(acc[1][2 * g + 1], ah[1], &bh[2]);
            }
        }
        slot = (slot == 2) ? 0 : slot + 1;
        pslot = (pslot == 2) ? 0 : pslot + 1;
    }

    if (SCATTER) {
        const float LOG2E_SC = 0.125f * 1.44269504088896340736f;
#pragma unroll
        for (int tm = 0; tm < 2; tm++)
#pragma unroll
            for (int nt = 0; nt < 8; nt++) {
                int f = n0 + wn + nt * 8 + (lane & 3) * 2;
                int cid = f >> 10;
                int hh = (f >> 6) & (HH - 1);
                int d = f & (DD - 1);
                float sc = (cid == 0) ? LOG2E_SC : 1.0f;
                __half* dst = (cid == 0) ? g_q16 : (cid == 1) ? g_k16 : g_v16;
#pragma unroll
                for (int half = 0; half < 2; half++) {
                    int row = m0 + wm + tm * 16 + (lane >> 2) + half * 8;
                    int b = row >> 11, s = row & (SS - 1);
                    size_t off = ((size_t)((b * HH + hh) * SS + s)) * DD + d;
                    *(unsigned*)&dst[off] = pack_h2(acc[tm][nt][half * 2] * sc,
                                                    acc[tm][nt][half * 2 + 1] * sc);
                }
            }
    } else {
#pragma unroll
        for (int tm = 0; tm < 2; tm++)
#pragma unroll
            for (int nt = 0; nt < 8; nt++) {
                int col = n0 + wn + nt * 8 + (lane & 3) * 2;
#pragma unroll
                for (int half = 0; half < 2; half++) {
                    int row = m0 + wm + tm * 16 + (lane >> 2) + half * 8;
                    float2 v = make_float2(acc[tm][nt][half * 2],
                                           acc[tm][nt][half * 2 + 1]);
                    *(float2*)&C[(size_t)row * NC + col] = v;
                }
            }
    }
}

// ---------------------------------------------------------------------------
// Flash attention v8: round-13 v6 (M_w=32, 4 warps, kv-tile 64, 3 CTAs/SM,
// 3-buffer KV ring) + hoisted loop-invariant Q fragments (saves 8 of 40
// LDSM.x4 per warp per kv tile).
// smem elems: Q[128*72] + 3 bufs x (K[64*72] + V[64*72]) = 73728 B
// ---------------------------------------------------------------------------
#define AT_Q 9216            // 128*72 elems
#define AT_T 4608            // 64*72 elems
#define AT8_SMEM ((AT_Q + 6 * AT_T) * 2)

__global__ __launch_bounds__(128, 3) void attn_mma8() {
    __half* smem = (__half*)dynsmem;
    const int tid = threadIdx.x, lane = tid & 31, w = tid >> 5;   // w 0..3
    const int q0 = blockIdx.x * 128, h = blockIdx.y, b = blockIdx.z;
    const size_t hb = (size_t)(b * HH + h) * SS * DD;

    const uint32_t uS = smem_u32(smem);
    const uint32_t uQ = uS;

    const int lm_r = lane & 15, lm_c = (lane >> 4) * 8;
    const int bn_r = (lane & 7) + (lane >> 4) * 8;
    const int bn_c = ((lane >> 3) & 1) * 8;

    unsigned bones[2];
    bones[0] = bones[1] = (lane < 4) ? 0x3C003C00u : 0u;

    auto kv_base = [&](int buf, int t) -> uint32_t {
        return uS + (AT_Q + (buf * 2 + t) * AT_T) * 2;
    };

    auto load_kv = [&](int buf, int kv) {
        const __half* s0 = g_k16 + hb + (size_t)kv * DD;
        const __half* s1 = g_v16 + hb + (size_t)kv * DD;
#pragma unroll
        for (int i = 0; i < 4; i++) {
            int idx = tid + i * 128;               // 0..511
            int r = idx >> 3, c8 = (idx & 7) * 8;  // r 0..63
            uint32_t so = (r * 72 + c8) * 2;
            int go = r * DD + c8;
            cp16(kv_base(buf, 0) + so, s0 + go);
            cp16(kv_base(buf, 1) + so, s1 + go);
        }
    };

    // Q load (128x64) + first two KV tiles
#pragma unroll
    for (int i = 0; i < 8; i++) {
        int idx = tid + i * 128;                   // 0..1023
        int r = idx >> 3, c8 = (idx & 7) * 8;      // r 0..127
        uint32_t so = (r * 72 + c8) * 2;
        size_t go = hb + (size_t)(q0 + r) * DD + c8;
        cp16(uQ + so, g_q16 + go);
    }
    load_kv(0, 0);  cp_commit();
    load_kv(1, 64); cp_commit();

    float m[4], l[4];
#pragma unroll
    for (int i = 0; i < 4; i++) { m[i] = -1.0e30f; l[i] = 0.0f; }
    float oacc[2][8][4];
#pragma unroll
    for (int tm = 0; tm < 2; tm++)
#pragma unroll
        for (int j = 0; j < 8; j++)
#pragma unroll
            for (int q = 0; q < 4; q++) oacc[tm][j][q] = 0.0f;

    unsigned aq[4][2][4];   // hoisted Q fragments (loaded once at ti==0)

    int slot = 0, pslot = 2;
#pragma unroll 1
    for (int ti = 0; ti < 32; ti++) {
        if (ti < 31) cp_wait<1>(); else cp_wait<0>();
        __syncthreads();

        if (ti + 2 < 32) {
            load_kv(pslot, (ti + 2) * 64);
            cp_commit();
        }

        if (ti == 0) {
            // Q arrived with commit-group 0 (waited above)
#pragma unroll
            for (int kt = 0; kt < 4; kt++)
#pragma unroll
                for (int tm = 0; tm < 2; tm++) {
                    uint32_t qoff =
                        ((w * 32 + tm * 16 + lm_r) * 72 + kt * 16 + lm_c) * 2;
                    ldsm4(aq[kt][tm], uQ + qoff);
                }
        }

        const uint32_t uK = kv_base(slot, 0);
        const uint32_t uV = kv_base(slot, 1);

        // S = Q @ K^T for 32 q rows (2 m-tiles)
        float sacc[2][8][4];
#pragma unroll
        for (int tm = 0; tm < 2; tm++)
#pragma unroll
            for (int j = 0; j < 8; j++)
#pragma unroll
                for (int q = 0; q < 4; q++) sacc[tm][j][q] = 0.0f;

#pragma unroll
        for (int kt = 0; kt < 4; kt++) {
#pragma unroll
            for (int g = 0; g < 4; g++) {
                unsigned bh[4];
                uint32_t koff = ((g * 16 + bn_r) * 72 + kt * 16 + bn_c) * 2;
                ldsm4(bh, uK + koff);
                mma_f16(sacc[0][2 * g],     aq[kt][0], &bh[0]);
                mma_f16(sacc[0][2 * g + 1], aq[kt][0], &bh[2]);
                mma_f16(sacc[1][2 * g],     aq[kt][1], &bh[0]);
                mma_f16(sacc[1][2 * g + 1], aq[kt][1], &bh[2]);
            }
        }

        // Row max (log2 domain), 4 row groups
        float mn[4], fac[4];
#pragma unroll
        for (int tm = 0; tm < 2; tm++) {
            float mxa = -1.0e30f, mxb = -1.0e30f;
#pragma unroll
            for (int nt = 0; nt < 8; nt++) {
                mxa = fmaxf(mxa, fmaxf(sacc[tm][nt][0], sacc[tm][nt][1]));
                mxb = fmaxf(mxb, fmaxf(sacc[tm][nt][2], sacc[tm][nt][3]));
            }
#pragma unroll
            for (int off = 1; off <= 2; off <<= 1) {
                mxa = fmaxf(mxa, __shfl_xor_sync(0xffffffffu, mxa, off));
                mxb = fmaxf(mxb, __shfl_xor_sync(0xffffffffu, mxb, off));
            }
            mn[2 * tm]     = fmaxf(m[2 * tm], mxa);
            mn[2 * tm + 1] = fmaxf(m[2 * tm + 1], mxb);
            fac[2 * tm]     = exp2f(m[2 * tm] - mn[2 * tm]);
            fac[2 * tm + 1] = exp2f(m[2 * tm + 1] - mn[2 * tm + 1]);
            m[2 * tm] = mn[2 * tm];
            m[2 * tm + 1] = mn[2 * tm + 1];
        }

        // rescale O
#pragma unroll
        for (int tm = 0; tm < 2; tm++)
#pragma unroll
            for (int nt = 0; nt < 8; nt++) {
                oacc[tm][nt][0] *= fac[2 * tm];
                oacc[tm][nt][1] *= fac[2 * tm];
                oacc[tm][nt][2] *= fac[2 * tm + 1];
                oacc[tm][nt][3] *= fac[2 * tm + 1];
            }

        // per-kt: build P, rowsum, PV (keeps P transient)
        float racc[2][4] = {{0, 0, 0, 0}, {0, 0, 0, 0}};
#pragma unroll
        for (int kt = 0; kt < 4; kt++) {
            unsigned ph[2][4];
#pragma unroll
            for (int tm = 0; tm < 2; tm++) {
                ph[tm][0] = h2_ex2(pack_h2(sacc[tm][2 * kt][0] - mn[2 * tm],
                                           sacc[tm][2 * kt][1] - mn[2 * tm]));
                ph[tm][1] = h2_ex2(pack_h2(sacc[tm][2 * kt][2] - mn[2 * tm + 1],
                                           sacc[tm][2 * kt][3] - mn[2 * tm + 1]));
                ph[tm][2] = h2_ex2(pack_h2(sacc[tm][2 * kt + 1][0] - mn[2 * tm],
                                           sacc[tm][2 * kt + 1][1] - mn[2 * tm]));
                ph[tm][3] = h2_ex2(pack_h2(sacc[tm][2 * kt + 1][2] - mn[2 * tm + 1],
                                           sacc[tm][2 * kt + 1][3] - mn[2 * tm + 1]));
                mma_f16(racc[tm], ph[tm], bones);
            }
#pragma unroll
            for (int dg = 0; dg < 4; dg++) {
                unsigned vh[4];
                uint32_t voff = ((kt * 16 + lm_r) * 72 + dg * 16 + lm_c) * 2;
                ldsm4t(vh, uV + voff);                 // shared across both m-tiles
                mma_f16(oacc[0][2 * dg],     ph[0], &vh[0]);
                mma_f16(oacc[0][2 * dg + 1], ph[0], &vh[2]);
                mma_f16(oacc[1][2 * dg],     ph[1], &vh[0]);
                mma_f16(oacc[1][2 * dg + 1], ph[1], &vh[2]);
            }
        }

        // fold row sums into l
#pragma unroll
        for (int tm = 0; tm < 2; tm++) {
            float rsa = __shfl_sync(0xffffffffu, racc[tm][0], 0, 4);
            float rsb = __shfl_sync(0xffffffffu, racc[tm][2], 0, 4);
            l[2 * tm]     = l[2 * tm] * fac[2 * tm] + rsa;
            l[2 * tm + 1] = l[2 * tm + 1] * fac[2 * tm + 1] + rsb;
        }

        __syncthreads();
        slot = (slot == 2) ? 0 : slot + 1;
        pslot = (pslot == 2) ? 0 : pslot + 1;
    }

    // normalize + store O (single fp16)
#pragma unroll
    for (int tm = 0; tm < 2; tm++) {
        float inva = 1.0f / l[2 * tm], invb = 1.0f / l[2 * tm + 1];
        int r1 = q0 + w * 32 + tm * 16 + (lane >> 2);
#pragma unroll
        for (int nt = 0; nt < 8; nt++) {
            int d = nt * 8 + (lane & 3) * 2;
            size_t off = ((size_t)(b * SS + r1)) * EE + h * DD + d;
            *(unsigned*)&g_o16[off] = pack_h2(oacc[tm][nt][0] * inva,
                                              oacc[tm][nt][1] * inva);
            off = ((size_t)(b * SS + r1 + 8)) * EE + h * DD + d;
            *(unsigned*)&g_o16[off] = pack_h2(oacc[tm][nt][2] * invb,
                                              oacc[tm][nt][3] * invb);
        }
    }
}

// ---------------------------------------------------------------------------
extern "C" void kernel_launch(void* const* d_in, const int* in_sizes, int n_in,
                              void* d_out, int out_size) {
    const float* x = (const float*)d_in[0];      // (B, S, E)
    const float* w_qkv = (const float*)d_in[1];  // (E, 3E)
    const float* w_out = (const float*)d_in[2];  // (E, E)
    float* out = (float*)d_out;                  // (B, S, E)

    __half *p_x, *p_wq, *p_wo, *p_o;
    cudaGetSymbolAddress((void**)&p_x, g_x16);
    cudaGetSymbolAddress((void**)&p_wq, g_wq16);
    cudaGetSymbolAddress((void**)&p_wo, g_wo16);
    cudaGetSymbolAddress((void**)&p_o, g_o16);

    // 0) convert all inputs in one launch
    conv3_kernel<<<(CN1 + CN2 + CN3 + 255) / 256, 256>>>(x, w_qkv, w_out,
                                                         p_x, p_wq, p_wo);

    // 1) QKV projection, scatter Q/K/V (Q pre-scaled by 0.125*log2e)
    cudaFuncSetAttribute(mma_gemm5<NQKV, true>,
                         cudaFuncAttributeMaxDynamicSharedMemorySize, G5_SMEM);
    mma_gemm5<NQKV, true><<<dim3(NQKV / 128, (BB * SS) / 128), 256, G5_SMEM>>>(
        p_x, p_wq, nullptr);

    // 2) Flash attention (M_w=32, kv=64, 3 CTAs/SM, hoisted Q)
    cudaFuncSetAttribute(attn_mma8, cudaFuncAttributeMaxDynamicSharedMemorySize,
                         AT8_SMEM);
    attn_mma8<<<dim3(SS / 128, HH, BB), 128, AT8_SMEM>>>();

    // 3) Output projection
    cudaFuncSetAttribute(mma_gemm5<EE, false>,
                         cudaFuncAttributeMaxDynamicSharedMemorySize, G5_SMEM);
    mma_gemm5<EE, false><<<dim3(EE / 128, (BB * SS) / 128), 256, G5_SMEM>>>(
        p_o, p_wo, out);
}

// round 16
// speedup vs baseline: 1.2125x; 1.2125x over previous
#include <cuda_runtime.h>
#include <cuda_fp16.h>
#include <cstdint>
#include <math.h>

#define BB 2
#define SS 2048
#define EE 1024
#define HH 16
#define DD 64
#define NQKV 3072

// ---------------------------------------------------------------------------
// Scratch (device globals — allocation-free). Plain fp16 everywhere.
// ---------------------------------------------------------------------------
__device__ __half g_x16[BB*SS*EE];       // x
__device__ __half g_wq16[EE*NQKV];       // w_qkv
__device__ __half g_wo16[EE*EE];         // w_out
__device__ __half g_q16[BB*HH*SS*DD];    // Q (pre-scaled by 0.125*log2e)
__device__ __half g_k16[BB*HH*SS*DD];
__device__ __half g_v16[BB*HH*SS*DD];
__device__ __half g_o16[BB*SS*EE];       // attention output

// single TU-wide dynamic smem symbol (char) — cast per kernel
extern __shared__ __align__(16) char dynsmem[];

// ---------------------------------------------------------------------------
// PTX wrappers
// ---------------------------------------------------------------------------
__device__ __forceinline__ void ldsm4(unsigned r[4], uint32_t a) {
    asm volatile("ldmatrix.sync.aligned.m8n8.x4.shared.b16 {%0,%1,%2,%3}, [%4];\n"
                 : "=r"(r[0]), "=r"(r[1]), "=r"(r[2]), "=r"(r[3]) : "r"(a));
}
__device__ __forceinline__ void ldsm4t(unsigned r[4], uint32_t a) {
    asm volatile("ldmatrix.sync.aligned.m8n8.x4.trans.shared.b16 {%0,%1,%2,%3}, [%4];\n"
                 : "=r"(r[0]), "=r"(r[1]), "=r"(r[2]), "=r"(r[3]) : "r"(a));
}
__device__ __forceinline__ void mma_f16(float c[4], const unsigned a[4], const unsigned b[2]) {
    asm volatile(
        "mma.sync.aligned.m16n8k16.row.col.f32.f16.f16.f32 "
        "{%0,%1,%2,%3}, {%4,%5,%6,%7}, {%8,%9}, {%0,%1,%2,%3};\n"
        : "+f"(c[0]), "+f"(c[1]), "+f"(c[2]), "+f"(c[3])
        : "r"(a[0]), "r"(a[1]), "r"(a[2]), "r"(a[3]), "r"(b[0]), "r"(b[1]));
}
__device__ __forceinline__ void cp16(uint32_t s, const void* g) {
    asm volatile("cp.async.cg.shared.global [%0], [%1], 16;\n" :: "r"(s), "l"(g));
}
__device__ __forceinline__ void cp_commit() {
    asm volatile("cp.async.commit_group;\n" ::: "memory");
}
template <int N>
__device__ __forceinline__ void cp_wait() {
    asm volatile("cp.async.wait_group %0;\n" :: "n"(N) : "memory");
}
__device__ __forceinline__ unsigned pack_h2(float x, float y) {
    __half2 h2 = __floats2half2_rn(x, y);
    return *reinterpret_cast<unsigned*>(&h2);
}
__device__ __forceinline__ unsigned h2_ex2(unsigned in) {
    unsigned out;
    asm("ex2.approx.f16x2 %0, %1;" : "=r"(out) : "r"(in));
    return out;
}
__device__ __forceinline__ uint32_t smem_u32(const void* p) {
    return (uint32_t)__cvta_generic_to_shared(p);
}

// ---------------------------------------------------------------------------
// Merged fp32 -> fp16 convert for x, w_qkv, w_out (single launch)
// ---------------------------------------------------------------------------
#define CN1 (BB*SS*EE/4)
#define CN2 (EE*NQKV/4)
#define CN3 (EE*EE/4)

__global__ __launch_bounds__(256) void conv3_kernel(const float* __restrict__ s1,
                                                    const float* __restrict__ s2,
                                                    const float* __restrict__ s3,
                                                    __half* __restrict__ d1,
                                                    __half* __restrict__ d2,
                                                    __half* __restrict__ d3) {
    int i = blockIdx.x * 256 + threadIdx.x;
    const float* src;
    __half* dst;
    int j;
    if (i < CN1)              { src = s1; dst = d1; j = i; }
    else if (i < CN1 + CN2)   { src = s2; dst = d2; j = i - CN1; }
    else if (i < CN1+CN2+CN3) { src = s3; dst = d3; j = i - CN1 - CN2; }
    else return;
    float4 v = *(const float4*)(src + (size_t)j * 4);
    *(uint2*)(dst + (size_t)j * 4) =
        make_uint2(pack_h2(v.x, v.y), pack_h2(v.z, v.w));
}

// ---------------------------------------------------------------------------
// fp16 GEMM: C[M, NC] = A[M,1024] @ W[1024,NC]
// BM=128, BN=128, BK=64, 8 warps, warp tile 32x64, 2 CTAs/SM.
// 3-stage cp.async ring, depth-2 prefetch, 1 sync per 64-deep k-tile.
// ---------------------------------------------------------------------------
#define ST_A 9216                          // 128*72 elems
#define ST_B 8704                          // 64*136 elems
#define ST_BYTES ((ST_A + ST_B) * 2)       // 35840 B
#define G5_SMEM (3 * ST_BYTES)             // 107520 B

template <int NC, bool SCATTER>
__global__ __launch_bounds__(256, 2) void mma_gemm5(const __half* __restrict__ A_g,
                                                    const __half* __restrict__ B_g,
                                                    float* __restrict__ C) {
    char* smem = dynsmem;
    const int tid = threadIdx.x;
    const int lane = tid & 31, wid = tid >> 5;
    const int wm = (wid & 3) * 32, wn = (wid >> 2) * 64;
    const int m0 = blockIdx.y * 128, n0 = blockIdx.x * 128;

    const uint32_t uS = smem_u32(smem);
    const int lm_r = lane & 15, lm_c = (lane >> 4) * 8;
    const uint32_t aoff0 = ((wm + lm_r) * 72 + lm_c) * 2;
    const uint32_t boff0 = (lm_r * 136 + wn + lm_c) * 2;

    float acc[2][8][4];
#pragma unroll
    for (int i = 0; i < 2; i++)
#pragma unroll
        for (int j = 0; j < 8; j++)
#pragma unroll
            for (int q = 0; q < 4; q++) acc[i][j][q] = 0.0f;

    auto load_tile = [&](int slot, int k0) {
        uint32_t base = uS + slot * ST_BYTES;
#pragma unroll
        for (int i = 0; i < 4; i++) {
            int idx = tid + i * 256;
            int r = idx >> 3, c8 = (idx & 7) * 8;
            cp16(base + (r * 72 + c8) * 2,
                 A_g + (size_t)(m0 + r) * EE + k0 + c8);
        }
        uint32_t bbase = base + ST_A * 2;
#pragma unroll
        for (int i = 0; i < 4; i++) {
            int idx = tid + i * 256;
            int r = idx >> 4, c8 = (idx & 15) * 8;
            cp16(bbase + (r * 136 + c8) * 2,
                 B_g + (size_t)(k0 + r) * NC + n0 + c8);
        }
    };

    load_tile(0, 0);  cp_commit();
    load_tile(1, 64); cp_commit();

    int slot = 0, pslot = 2;
#pragma unroll 1
    for (int kt = 0; kt < 16; kt++) {
        if (kt < 15) cp_wait<1>(); else cp_wait<0>();
        __syncthreads();

        if (kt + 2 < 16) {
            load_tile(pslot, (kt + 2) * 64);
            cp_commit();
        }

        const uint32_t uA = uS + slot * ST_BYTES;
        const uint32_t uB = uA + ST_A * 2;

#pragma unroll
        for (int ks = 0; ks < 4; ks++) {
            const int kk = ks * 16;
            unsigned ah[2][4];
#pragma unroll
            for (int tm = 0; tm < 2; tm++) {
                uint32_t off = aoff0 + (tm * 16 * 72 + kk) * 2;
                ldsm4(ah[tm], uA + off);
            }
#pragma unroll
            for (int g = 0; g < 4; g++) {
                unsigned bh[4];
                uint32_t off = boff0 + (kk * 136 + g * 16) * 2;
                ldsm4t(bh, uB + off);
                mma_f16(acc[0][2 * g],     ah[0], &bh[0]);
                mma_f16(acc[0][2 * g + 1], ah[0], &bh[2]);
                mma_f16(acc[1][2 * g],     ah[1], &bh[0]);
                mma_f16(acc[1][2 * g + 1], ah[1], &bh[2]);
            }
        }
        slot = (slot == 2) ? 0 : slot + 1;
        pslot = (pslot == 2) ? 0 : pslot + 1;
    }

    if (SCATTER) {
        const float LOG2E_SC = 0.125f * 1.44269504088896340736f;
#pragma unroll
        for (int tm = 0; tm < 2; tm++)
#pragma unroll
            for (int nt = 0; nt < 8; nt++) {
                int f = n0 + wn + nt * 8 + (lane & 3) * 2;
                int cid = f >> 10;
                int hh = (f >> 6) & (HH - 1);
                int d = f & (DD - 1);
                float sc = (cid == 0) ? LOG2E_SC : 1.0f;
                __half* dst = (cid == 0) ? g_q16 : (cid == 1) ? g_k16 : g_v16;
#pragma unroll
                for (int half = 0; half < 2; half++) {
                    int row = m0 + wm + tm * 16 + (lane >> 2) + half * 8;
                    int b = row >> 11, s = row & (SS - 1);
                    size_t off = ((size_t)((b * HH + hh) * SS + s)) * DD + d;
                    *(unsigned*)&dst[off] = pack_h2(acc[tm][nt][half * 2] * sc,
                                                    acc[tm][nt][half * 2 + 1] * sc);
                }
            }
    } else {
#pragma unroll
        for (int tm = 0; tm < 2; tm++)
#pragma unroll
            for (int nt = 0; nt < 8; nt++) {
                int col = n0 + wn + nt * 8 + (lane & 3) * 2;
#pragma unroll
                for (int half = 0; half < 2; half++) {
                    int row = m0 + wm + tm * 16 + (lane >> 2) + half * 8;
                    float2 v = make_float2(acc[tm][nt][half * 2],
                                           acc[tm][nt][half * 2 + 1]);
                    *(float2*)&C[(size_t)row * NC + col] = v;
                }
            }
    }
}

// ---------------------------------------------------------------------------
// Flash attention (round-13 config): M_w=32 (4 warps x 32 q rows per 128-row
// CTA), 128 threads, 3 CTAs/SM, kv-tile 64, 3-buffer KV ring (depth 2).
// fp16 mma, log2-domain softmax with fp16 ex2, rowsum via ones-MMA.
// ONE barrier per kv tile (trailing barrier proven redundant by the ring's
// depth-2 prefetch: prefetch at ti writes slot (ti+2)%3, last read at ti-1,
// and the top barrier at ti already orders all warps past ti-1).
// smem elems: Q[128*72] + 3 bufs x (K[64*72] + V[64*72]) = 73728 B
// ---------------------------------------------------------------------------
#define AT_Q 9216            // 128*72 elems
#define AT_T 4608            // 64*72 elems
#define AT6_SMEM ((AT_Q + 6 * AT_T) * 2)

__global__ __launch_bounds__(128, 3) void attn_mma6() {
    __half* smem = (__half*)dynsmem;
    const int tid = threadIdx.x, lane = tid & 31, w = tid >> 5;   // w 0..3
    const int q0 = blockIdx.x * 128, h = blockIdx.y, b = blockIdx.z;
    const size_t hb = (size_t)(b * HH + h) * SS * DD;

    const uint32_t uS = smem_u32(smem);
    const uint32_t uQ = uS;

    const int lm_r = lane & 15, lm_c = (lane >> 4) * 8;
    const int bn_r = (lane & 7) + (lane >> 4) * 8;
    const int bn_c = ((lane >> 3) & 1) * 8;

    unsigned bones[2];
    bones[0] = bones[1] = (lane < 4) ? 0x3C003C00u : 0u;

    auto kv_base = [&](int buf, int t) -> uint32_t {
        return uS + (AT_Q + (buf * 2 + t) * AT_T) * 2;
    };

    auto load_kv = [&](int buf, int kv) {
        const __half* s0 = g_k16 + hb + (size_t)kv * DD;
        const __half* s1 = g_v16 + hb + (size_t)kv * DD;
#pragma unroll
        for (int i = 0; i < 4; i++) {
            int idx = tid + i * 128;               // 0..511
            int r = idx >> 3, c8 = (idx & 7) * 8;  // r 0..63
            uint32_t so = (r * 72 + c8) * 2;
            int go = r * DD + c8;
            cp16(kv_base(buf, 0) + so, s0 + go);
            cp16(kv_base(buf, 1) + so, s1 + go);
        }
    };

    // Q load (128x64) + first two KV tiles
#pragma unroll
    for (int i = 0; i < 8; i++) {
        int idx = tid + i * 128;                   // 0..1023
        int r = idx >> 3, c8 = (idx & 7) * 8;      // r 0..127
        uint32_t so = (r * 72 + c8) * 2;
        size_t go = hb + (size_t)(q0 + r) * DD + c8;
        cp16(uQ + so, g_q16 + go);
    }
    load_kv(0, 0);  cp_commit();
    load_kv(1, 64); cp_commit();

    // per-warp rows: [w*32, w*32+32). Row groups (per tm): lane>>2 and +8.
    float m[4], l[4];
#pragma unroll
    for (int i = 0; i < 4; i++) { m[i] = -1.0e30f; l[i] = 0.0f; }
    float oacc[2][8][4];
#pragma unroll
    for (int tm = 0; tm < 2; tm++)
#pragma unroll
        for (int j = 0; j < 8; j++)
#pragma unroll
            for (int q = 0; q < 4; q++) oacc[tm][j][q] = 0.0f;

    int slot = 0, pslot = 2;
#pragma unroll 1
    for (int ti = 0; ti < 32; ti++) {
        if (ti < 31) cp_wait<1>(); else cp_wait<0>();
        __syncthreads();

        if (ti + 2 < 32) {
            load_kv(pslot, (ti + 2) * 64);
            cp_commit();
        }

        const uint32_t uK = kv_base(slot, 0);
        const uint32_t uV = kv_base(slot, 1);

        // S = Q @ K^T for 32 q rows (2 m-tiles)
        float sacc[2][8][4];
#pragma unroll
        for (int tm = 0; tm < 2; tm++)
#pragma unroll
            for (int j = 0; j < 8; j++)
#pragma unroll
                for (int q = 0; q < 4; q++) sacc[tm][j][q] = 0.0f;

#pragma unroll
        for (int kt = 0; kt < 4; kt++) {
            unsigned aq[2][4];
#pragma unroll
            for (int tm = 0; tm < 2; tm++) {
                uint32_t qoff = ((w * 32 + tm * 16 + lm_r) * 72 + kt * 16 + lm_c) * 2;
                ldsm4(aq[tm], uQ + qoff);
            }
#pragma unroll
            for (int g = 0; g < 4; g++) {
                unsigned bh[4];
                uint32_t koff = ((g * 16 + bn_r) * 72 + kt * 16 + bn_c) * 2;
                ldsm4(bh, uK + koff);
                mma_f16(sacc[0][2 * g],     aq[0], &bh[0]);
                mma_f16(sacc[0][2 * g + 1], aq[0], &bh[2]);
                mma_f16(sacc[1][2 * g],     aq[1], &bh[0]);
                mma_f16(sacc[1][2 * g + 1], aq[1], &bh[2]);
            }
        }

        // Row max (log2 domain), 4 row groups
        float mn[4], fac[4];
#pragma unroll
        for (int tm = 0; tm < 2; tm++) {
            float mxa = -1.0e30f, mxb = -1.0e30f;
#pragma unroll
            for (int nt = 0; nt < 8; nt++) {
                mxa = fmaxf(mxa, fmaxf(sacc[tm][nt][0], sacc[tm][nt][1]));
                mxb = fmaxf(mxb, fmaxf(sacc[tm][nt][2], sacc[tm][nt][3]));
            }
#pragma unroll
            for (int off = 1; off <= 2; off <<= 1) {
                mxa = fmaxf(mxa, __shfl_xor_sync(0xffffffffu, mxa, off));
                mxb = fmaxf(mxb, __shfl_xor_sync(0xffffffffu, mxb, off));
            }
            mn[2 * tm]     = fmaxf(m[2 * tm], mxa);
            mn[2 * tm + 1] = fmaxf(m[2 * tm + 1], mxb);
            fac[2 * tm]     = exp2f(m[2 * tm] - mn[2 * tm]);
            fac[2 * tm + 1] = exp2f(m[2 * tm + 1] - mn[2 * tm + 1]);
            m[2 * tm] = mn[2 * tm];
            m[2 * tm + 1] = mn[2 * tm + 1];
        }

        // rescale O
#pragma unroll
        for (int tm = 0; tm < 2; tm++)
#pragma unroll
            for (int nt = 0; nt < 8; nt++) {
                oacc[tm][nt][0] *= fac[2 * tm];
                oacc[tm][nt][1] *= fac[2 * tm];
                oacc[tm][nt][2] *= fac[2 * tm + 1];
                oacc[tm][nt][3] *= fac[2 * tm + 1];
            }

        // per-kt: build P, rowsum, PV (keeps P transient)
        float racc[2][4] = {{0, 0, 0, 0}, {0, 0, 0, 0}};
#pragma unroll
        for (int kt = 0; kt < 4; kt++) {
            unsigned ph[2][4];
#pragma unroll
            for (int tm = 0; tm < 2; tm++) {
                ph[tm][0] = h2_ex2(pack_h2(sacc[tm][2 * kt][0] - mn[2 * tm],
                                           sacc[tm][2 * kt][1] - mn[2 * tm]));
                ph[tm][1] = h2_ex2(pack_h2(sacc[tm][2 * kt][2] - mn[2 * tm + 1],
                                           sacc[tm][2 * kt][3] - mn[2 * tm + 1]));
                ph[tm][2] = h2_ex2(pack_h2(sacc[tm][2 * kt + 1][0] - mn[2 * tm],
                                           sacc[tm][2 * kt + 1][1] - mn[2 * tm]));
                ph[tm][3] = h2_ex2(pack_h2(sacc[tm][2 * kt + 1][2] - mn[2 * tm + 1],
                                           sacc[tm][2 * kt + 1][3] - mn[2 * tm + 1]));
                mma_f16(racc[tm], ph[tm], bones);
            }
#pragma unroll
            for (int dg = 0; dg < 4; dg++) {
                unsigned vh[4];
                uint32_t voff = ((kt * 16 + lm_r) * 72 + dg * 16 + lm_c) * 2;
                ldsm4t(vh, uV + voff);                 // shared across both m-tiles
                mma_f16(oacc[0][2 * dg],     ph[0], &vh[0]);
                mma_f16(oacc[0][2 * dg + 1], ph[0], &vh[2]);
                mma_f16(oacc[1][2 * dg],     ph[1], &vh[0]);
                mma_f16(oacc[1][2 * dg + 1], ph[1], &vh[2]);
            }
        }

        // fold row sums into l
#pragma unroll
        for (int tm = 0; tm < 2; tm++) {
            float rsa = __shfl_sync(0xffffffffu, racc[tm][0], 0, 4);
            float rsb = __shfl_sync(0xffffffffu, racc[tm][2], 0, 4);
            l[2 * tm]     = l[2 * tm] * fac[2 * tm] + rsa;
            l[2 * tm + 1] = l[2 * tm + 1] * fac[2 * tm + 1] + rsb;
        }

        slot = (slot == 2) ? 0 : slot + 1;
        pslot = (pslot == 2) ? 0 : pslot + 1;
    }

    // normalize + store O (single fp16)
#pragma unroll
    for (int tm = 0; tm < 2; tm++) {
        float inva = 1.0f / l[2 * tm], invb = 1.0f / l[2 * tm + 1];
        int r1 = q0 + w * 32 + tm * 16 + (lane >> 2);
#pragma unroll
        for (int nt = 0; nt < 8; nt++) {
            int d = nt * 8 + (lane & 3) * 2;
            size_t off = ((size_t)(b * SS + r1)) * EE + h * DD + d;
            *(unsigned*)&g_o16[off] = pack_h2(oacc[tm][nt][0] * inva,
                                              oacc[tm][nt][1] * inva);
            off = ((size_t)(b * SS + r1 + 8)) * EE + h * DD + d;
            *(unsigned*)&g_o16[off] = pack_h2(oacc[tm][nt][2] * invb,
                                              oacc[tm][nt][3] * invb);
        }
    }
}

// ---------------------------------------------------------------------------
extern "C" void kernel_launch(void* const* d_in, const int* in_sizes, int n_in,
                              void* d_out, int out_size) {
    const float* x = (const float*)d_in[0];      // (B, S, E)
    const float* w_qkv = (const float*)d_in[1];  // (E, 3E)
    const float* w_out = (const float*)d_in[2];  // (E, E)
    float* out = (float*)d_out;                  // (B, S, E)

    __half *p_x, *p_wq, *p_wo, *p_o;
    cudaGetSymbolAddress((void**)&p_x, g_x16);
    cudaGetSymbolAddress((void**)&p_wq, g_wq16);
    cudaGetSymbolAddress((void**)&p_wo, g_wo16);
    cudaGetSymbolAddress((void**)&p_o, g_o16);

    // 0) convert all inputs in one launch
    conv3_kernel<<<(CN1 + CN2 + CN3 + 255) / 256, 256>>>(x, w_qkv, w_out,
                                                         p_x, p_wq, p_wo);

    // 1) QKV projection, scatter Q/K/V (Q pre-scaled by 0.125*log2e)
    cudaFuncSetAttribute(mma_gemm5<NQKV, true>,
                         cudaFuncAttributeMaxDynamicSharedMemorySize, G5_SMEM);
    mma_gemm5<NQKV, true><<<dim3(NQKV / 128, (BB * SS) / 128), 256, G5_SMEM>>>(
        p_x, p_wq, nullptr);

    // 2) Flash attention (M_w=32, kv=64, 3 CTAs/SM, single barrier per tile)
    cudaFuncSetAttribute(attn_mma6, cudaFuncAttributeMaxDynamicSharedMemorySize,
                         AT6_SMEM);
    attn_mma6<<<dim3(SS / 128, HH, BB), 128, AT6_SMEM>>>();

    // 3) Output projection
    cudaFuncSetAttribute(mma_gemm5<EE, false>,
                         cudaFuncAttributeMaxDynamicSharedMemorySize, G5_SMEM);
    mma_gemm5<EE, false><<<dim3(EE / 128, (BB * SS) / 128), 256, G5_SMEM>>>(
        p_o, p_wo, out);
}